// round 6
// baseline (speedup 1.0000x reference)
#include <cuda_runtime.h>
#include <stdint.h>

#define N1 12800          // 100*128 elements of tm1
#define N2 25600          // 100*256 elements of tm2
#define NT 38400
#define K1 6399           // (N1-1)//2 -> torch lower-median rank
#define K2 12799
#define NBLOCKS 148
#define EPB 260           // 148*260 = 38480 >= 38400
#define R 4               // histogram / bucket replicas
#define CAPR 256          // per-replica bucket capacity
#define SMALL 512         // fast-path limit on selected-bin population

// -------- device scratch (reset in-kernel every run) ----------------------
__device__ unsigned int g_keys[NT];                  // fallback-path data
__device__ float        g_w[NT];
__device__ unsigned int g_bcnt[R][2][2048];          // replicated count hists
__device__ float        g_whist[R][2][2048];         // replicated weight hists
__device__ unsigned int g_bkey[2][2048][R][CAPR];    // sub-bucketed keys
__device__ float        g_bw  [2][2048][R][CAPR];    // sub-bucketed weights
__device__ double       g_sum_p1, g_sum_p2;          // sum (t - vmask)^2
__device__ double       g_sum_a1, g_sum_a2;          // sum amask^2
__device__ unsigned int g_arrive;

__device__ __forceinline__ unsigned int mono(unsigned int u) {
    return u ^ ((unsigned int)((int)u >> 31) | 0x80000000u);
}

// ------------------- fallback-only helpers (block-wide) -------------------
__device__ unsigned int block_select(const unsigned int* hist, int nb,
                                     unsigned int* warpbuf,
                                     unsigned int* k_sh, unsigned int* sel_sh)
{
    int tid  = threadIdx.x;
    int lane = tid & 31;
    int warp = tid >> 5;
    int bpt  = nb >> 10;
    int base = tid * bpt;

    unsigned int local = 0;
    for (int j = 0; j < bpt; j++) local += hist[base + j];

    unsigned int incl = local;
    #pragma unroll
    for (int o = 1; o < 32; o <<= 1) {
        unsigned int t = __shfl_up_sync(0xffffffffu, incl, o);
        if (lane >= o) incl += t;
    }
    if (lane == 31) warpbuf[warp] = incl;
    __syncthreads();
    if (warp == 0) {
        unsigned int w = warpbuf[lane];
        unsigned int wi = w;
        #pragma unroll
        for (int o = 1; o < 32; o <<= 1) {
            unsigned int t = __shfl_up_sync(0xffffffffu, wi, o);
            if (lane >= o) wi += t;
        }
        warpbuf[lane] = wi - w;
    }
    __syncthreads();

    unsigned int ex = (incl - local) + warpbuf[warp];
    unsigned int k = *k_sh;
    __syncthreads();

    unsigned int c = ex;
    for (int j = 0; j < bpt; j++) {
        unsigned int h = hist[base + j];
        if (k >= c && k < c + h) {
            *sel_sh = (unsigned int)(base + j);
            *k_sh   = k - c;
        }
        c += h;
    }
    __syncthreads();
    return *sel_sh;
}

__device__ float block_sum(float v, float* redf)
{
    int lane = threadIdx.x & 31;
    int warp = threadIdx.x >> 5;
    #pragma unroll
    for (int o = 16; o; o >>= 1) v += __shfl_down_sync(0xffffffffu, v, o);
    if (lane == 0) redf[warp] = v;
    __syncthreads();
    if (warp == 0) {
        float r = redf[lane];
        #pragma unroll
        for (int o = 16; o; o >>= 1) r += __shfl_down_sync(0xffffffffu, r, o);
        if (lane == 0) redf[0] = r;
    }
    __syncthreads();
    float r = redf[0];
    __syncthreads();
    return r;
}

// ---------------------------------------------------------------------------
__global__ void __launch_bounds__(1024) fused_kernel(
    const float* __restrict__ c2,  const float* __restrict__ c3,
    const float* __restrict__ vm1, const float* __restrict__ vm2,
    const float* __restrict__ am1, const float* __restrict__ am2,
    float* __restrict__ out)
{
    __shared__ unsigned int wt_c[2][16];
    __shared__ float        wt_w[2][16];
    __shared__ unsigned int d0_sh[2], kin_sh[2];
    __shared__ float        suf_sh[2];
    __shared__ unsigned int sk[2][SMALL];
    __shared__ float        sw[2][SMALL];
    __shared__ unsigned int mkey_sh[2];
    __shared__ float        S_sh[2];
    __shared__ unsigned int ovf_sh[2];
    __shared__ unsigned int fb_hist[2048];
    __shared__ unsigned int warpbuf[32];
    __shared__ float        redf[32];
    __shared__ unsigned int k_sh, sel_sh;
    __shared__ float        shp1[32], shp2[32], sha1[32], sha2[32];
    __shared__ bool         is_last_sh;

    int tid  = threadIdx.x;
    int lane = tid & 31;
    int warp = tid >> 5;

    // ===================== gather (all blocks, EPB elems each) ==============
    float p1 = 0.f, p2 = 0.f, a1s = 0.f, a2s = 0.f;
    int e = blockIdx.x * EPB + tid;
    if (tid < EPB && e < NT) {
        float t, v, a;
        int arr;
        if (e < N1) {
            t = c2[(size_t)e * 3136 + 399];         // [.,.,7,7]: 7*56+7
            v = vm1[e]; a = am1[e]; arr = 0;
        } else {
            int idx = e - N1;
            t = c3[(size_t)idx * 784 + 87];         // [.,.,3,3]: 3*28+3
            v = vm2[idx]; a = am2[idx]; arr = 1;
        }
        unsigned int key = mono(__float_as_uint(t));
        float w = 1.0f - 2.0f * a;
        g_keys[e] = key;
        g_w[e]    = w;
        unsigned int bin = key >> 21;
        int r = blockIdx.x & (R - 1);
        unsigned int pos = atomicAdd(&g_bcnt[r][arr][bin], 1u);
        if (pos < CAPR) {
            g_bkey[arr][bin][r][pos] = key;
            g_bw[arr][bin][r][pos]   = w;
        }
        atomicAdd(&g_whist[r][arr][bin], w);
        float d = t - v;
        if (arr == 0) { p1 = d * d; a1s = a * a; }
        else          { p2 = d * d; a2s = a * a; }
    }
    #pragma unroll
    for (int o = 16; o; o >>= 1) {
        p1  += __shfl_down_sync(0xffffffffu, p1,  o);
        p2  += __shfl_down_sync(0xffffffffu, p2,  o);
        a1s += __shfl_down_sync(0xffffffffu, a1s, o);
        a2s += __shfl_down_sync(0xffffffffu, a2s, o);
    }
    if (lane == 0) { shp1[warp] = p1; shp2[warp] = p2;
                     sha1[warp] = a1s; sha2[warp] = a2s; }
    __syncthreads();

    // warp 0: final block reduce + one atomic per sum + arrival
    if (warp == 0) {
        float x1 = shp1[lane], x2 = shp2[lane], x3 = sha1[lane], x4 = sha2[lane];
        #pragma unroll
        for (int o = 16; o; o >>= 1) {
            x1 += __shfl_down_sync(0xffffffffu, x1, o);
            x2 += __shfl_down_sync(0xffffffffu, x2, o);
            x3 += __shfl_down_sync(0xffffffffu, x3, o);
            x4 += __shfl_down_sync(0xffffffffu, x4, o);
        }
        if (lane == 0) {
            atomicAdd(&g_sum_p1, (double)x1);
            atomicAdd(&g_sum_p2, (double)x2);
            atomicAdd(&g_sum_a1, (double)x3);
            atomicAdd(&g_sum_a2, (double)x4);
            __threadfence();
            unsigned int rr = atomicAdd(&g_arrive, 1u);
            is_last_sh = (rr == (unsigned int)(NBLOCKS - 1));
        }
    }
    __syncthreads();
    if (!is_last_sh) return;

    // ===================== finalize (last block only) =======================
    // early loads of the global sums (values used only at the very end)
    double sp1 = __ldcg(&g_sum_p1);
    double sp2 = __ldcg(&g_sum_p2);
    double sa1 = __ldcg(&g_sum_a1);
    double sa2 = __ldcg(&g_sum_a2);

    int half    = tid >> 9;          // == arr for this half
    int htid    = tid & 511;
    int hwarp   = htid >> 5;         // 0..15
    int arr     = half;
    int binbase = htid << 2;         // 4 bins per thread

    // ---- load + sum replicated hists into registers (32 MLP'd loads)
    unsigned int cnt[4] = {0u, 0u, 0u, 0u};
    float        wsm[4] = {0.f, 0.f, 0.f, 0.f};
    #pragma unroll
    for (int r = 0; r < R; r++)
        #pragma unroll
        for (int j = 0; j < 4; j++) {
            cnt[j] += __ldcg(&g_bcnt[r][arr][binbase + j]);
            wsm[j] += __ldcg(&g_whist[r][arr][binbase + j]);
        }
    // reset weight hists now (fire-and-forget stores)
    #pragma unroll
    for (int r = 0; r < R; r++)
        #pragma unroll
        for (int j = 0; j < 4; j++)
            g_whist[r][arr][binbase + j] = 0.f;

    // ---- fused level-1 select + suffix-weight (2 barriers)
    unsigned int lc = cnt[0] + cnt[1] + cnt[2] + cnt[3];
    float        lw = wsm[0] + wsm[1] + wsm[2] + wsm[3];
    unsigned int ic = lc; float iw = lw;
    #pragma unroll
    for (int o = 1; o < 32; o <<= 1) {
        unsigned int tc = __shfl_up_sync(0xffffffffu, ic, o);
        float        tw = __shfl_up_sync(0xffffffffu, iw, o);
        if (lane >= o) { ic += tc; iw += tw; }
    }
    if (lane == 31) { wt_c[half][hwarp] = ic; wt_w[half][hwarp] = iw; }
    __syncthreads();

    unsigned int tc = (lane < 16) ? wt_c[half][lane] : 0u;
    float        tw = (lane < 16) ? wt_w[half][lane] : 0.f;
    #pragma unroll
    for (int o = 1; o < 16; o <<= 1) {
        unsigned int uc = __shfl_up_sync(0xffffffffu, tc, o);
        float        uw = __shfl_up_sync(0xffffffffu, tw, o);
        if (lane >= o) { tc += uc; tw += uw; }
    }
    float total_w = __shfl_sync(0xffffffffu, tw, 15);
    unsigned int woff_c = hwarp ? __shfl_sync(0xffffffffu, tc, hwarp - 1) : 0u;
    float        woff_w = hwarp ? __shfl_sync(0xffffffffu, tw, hwarp - 1) : 0.f;

    unsigned int ex  = woff_c + (ic - lc);
    float        exw = woff_w + (iw - lw);
    unsigned int K   = arr ? K2 : K1;
    {
        unsigned int c = ex; float wp = exw;
        #pragma unroll
        for (int j = 0; j < 4; j++) {
            if (K >= c && K < c + cnt[j]) {
                d0_sh[half]  = (unsigned int)(binbase + j);
                kin_sh[half] = K - c;
                suf_sh[half] = total_w - (wp + wsm[j]);
            }
            c += cnt[j]; wp += wsm[j];
        }
    }
    __syncthreads();

    unsigned int d0  = d0_sh[half];
    unsigned int kin = kin_sh[half];

    // ---- replica counts of selected bin, overflow check
    unsigned int c0 = __ldcg(&g_bcnt[0][arr][d0]);
    unsigned int c1 = __ldcg(&g_bcnt[1][arr][d0]);
    unsigned int cc2 = __ldcg(&g_bcnt[2][arr][d0]);
    unsigned int cc3 = __ldcg(&g_bcnt[3][arr][d0]);
    unsigned int o1 = c0, o2 = o1 + c1, o3 = o2 + cc2;
    unsigned int nc = o3 + cc3;
    if (htid == 0)
        ovf_sh[half] = (c0 > CAPR || c1 > CAPR || cc2 > CAPR || cc3 > CAPR ||
                        nc > SMALL) ? 1u : 0u;

    // reset count hists (no longer needed; fire-and-forget)
    #pragma unroll
    for (int r = 0; r < R; r++)
        #pragma unroll
        for (int j = 0; j < 4; j++)
            g_bcnt[r][arr][binbase + j] = 0u;
    __syncthreads();

    if (!(ovf_sh[0] | ovf_sh[1])) {
        // =============== fast path: small-set median, both halves ==========
        if (htid < (int)nc) {
            int r, p;
            if      (htid >= (int)o3) { r = 3; p = htid - (int)o3; }
            else if (htid >= (int)o2) { r = 2; p = htid - (int)o2; }
            else if (htid >= (int)o1) { r = 1; p = htid - (int)o1; }
            else                      { r = 0; p = htid; }
            sk[half][htid] = __ldcg(&g_bkey[arr][d0][r][p]);
            sw[half][htid] = __ldcg(&g_bw[arr][d0][r][p]);
        }
        __syncthreads();
        if (htid < (int)nc) {
            unsigned int key = sk[half][htid];
            unsigned int less = 0, eq = 0;
            for (unsigned int j = 0; j < nc; j++) {
                unsigned int kj = sk[half][j];
                less += (kj < key);
                eq   += (kj == key);
            }
            if (less <= kin && kin < less + eq) mkey_sh[half] = key;
        }
        __syncthreads();
        unsigned int mkey = mkey_sh[half];
        float s = (htid < (int)nc && sk[half][htid] >= mkey) ? sw[half][htid] : 0.f;
        #pragma unroll
        for (int o = 16; o; o >>= 1) s += __shfl_down_sync(0xffffffffu, s, o);
        if (lane == 0) wt_w[half][hwarp] = s;
        __syncthreads();
        if (htid == 0) {
            float t = 0.f;
            #pragma unroll
            for (int j = 0; j < 16; j++) t += wt_w[half][j];
            S_sh[half] = suf_sh[half] + t;
        }
    } else {
        // =============== fallback: block-wide rescan per array =============
        for (int a2 = 0; a2 < 2; a2++) {
            unsigned int fd0 = d0_sh[a2];
            int base = a2 ? N1 : 0;
            int n    = a2 ? N2 : N1;
            if (tid == 0) k_sh = kin_sh[a2];
            for (int b = tid; b < 2048; b += 1024) fb_hist[b] = 0u;
            __syncthreads();
            for (int j = base + tid; j < base + n; j += 1024) {
                unsigned int key = __ldcg(&g_keys[j]);
                if ((key >> 21) == fd0) atomicAdd(&fb_hist[(key >> 10) & 2047u], 1u);
            }
            __syncthreads();
            unsigned int d1 = block_select(fb_hist, 2048, warpbuf, &k_sh, &sel_sh);
            unsigned int p21 = (fd0 << 11) | d1;
            fb_hist[tid] = 0u;
            __syncthreads();
            for (int j = base + tid; j < base + n; j += 1024) {
                unsigned int key = __ldcg(&g_keys[j]);
                if ((key >> 10) == p21) atomicAdd(&fb_hist[key & 1023u], 1u);
            }
            __syncthreads();
            unsigned int d2 = block_select(fb_hist, 1024, warpbuf, &k_sh, &sel_sh);
            unsigned int mkey = (p21 << 10) | d2;
            float s = 0.f;
            for (int j = base + tid; j < base + n; j += 1024) {
                unsigned int key = __ldcg(&g_keys[j]);
                if ((key >> 21) == fd0 && key >= mkey) s += __ldcg(&g_w[j]);
            }
            s = block_sum(s, redf);
            if (tid == 0) S_sh[a2] = suf_sh[a2] + s;
            __syncthreads();
        }
    }
    __syncthreads();

    // ===================== output + remaining state reset ===================
    if (tid == 0) {
        double p = (sqrt(sp1) + sqrt(sp2)) * (1.0 / 38400.0);
        double q1sq = sa1 + (double)S_sh[0];
        double q2sq = sa2 + (double)S_sh[1];
        double q = (sqrt(q1sq) + sqrt(q2sq)) * (1.0 / 384.0);
        out[0] = (float)p;
        out[1] = (float)q;
        g_sum_p1 = 0.0; g_sum_p2 = 0.0;
        g_sum_a1 = 0.0; g_sum_a2 = 0.0;
        g_arrive = 0u;
    }
}

// ---------------------------------------------------------------------------
extern "C" void kernel_launch(void* const* d_in, const int* in_sizes, int n_in,
                              void* d_out, int out_size)
{
    const float* c2  = (const float*)d_in[0];
    const float* c3  = (const float*)d_in[1];
    const float* vm1 = (const float*)d_in[2];
    const float* vm2 = (const float*)d_in[3];
    const float* am1 = (const float*)d_in[4];
    const float* am2 = (const float*)d_in[5];
    float* out = (float*)d_out;

    fused_kernel<<<NBLOCKS, 1024>>>(c2, c3, vm1, vm2, am1, am2, out);
}